// round 16
// baseline (speedup 1.0000x reference)
#include <cuda_runtime.h>
#include <cstdint>

// DilatedReparamBlock == single 13x13 depthwise conv + per-channel bias.
//
// R15 = R14 (mt-outer tf32 Toeplitz GEMM, 211us) with the HMMA accumulator
// RAW chain split in two: even-ks and odd-ks accumulate into independent
// register quads, summed at the end. R14 showed nothing saturated
// (L1 67%, tensor 24%, issue 42%) == latency-bound on the 33-deep serial
// MMA chain; two chains double tensor ILP per warp. +4 regs (~88, under
// the 97 cap at launch_bounds(224,3)).

#define CC   256
#define HW   56
#define PAD  6
#define TROWS 69              // 68 padded rows + 1 zero row for K-padding
#define TCOLS 68
#define TILE (TROWS * TCOLS)  // 4692
#define NKS  33               // K = 264 = 33 * 8 (13*20=260 real + 4 zero)
#define NTHR 224              // 7 warps; warp w <-> output col block xb = w

__device__ uint2 g_B2[CC * NKS * 32];  // (tf32 B[8ks+tig][g], B[8ks+tig+4][g])
__device__ float g_bias[CC];

static __device__ __forceinline__ uint32_t f2tf32(float v)
{
    uint32_t u;
    asm("cvt.rna.tf32.f32 %0, %1;" : "=r"(u) : "f"(v));
    return u;
}

__global__ void prep_kernel(const float* __restrict__ lk_w,
                            const float* __restrict__ w0, const float* __restrict__ w1,
                            const float* __restrict__ w2, const float* __restrict__ w3,
                            const float* __restrict__ w4, const float* __restrict__ w5,
                            const float* __restrict__ gamma, const float* __restrict__ beta,
                            const float* __restrict__ mean,  const float* __restrict__ var)
{
    __shared__ float sweq[169];
    int c = blockIdx.x;
    int t = threadIdx.x;

    float s[7], sh[7];
#pragma unroll
    for (int i = 0; i < 7; i++) {
        float sc = gamma[i * CC + c] * rsqrtf(var[i * CC + c] + 1e-5f);
        s[i]  = sc;
        sh[i] = beta[i * CC + c] - mean[i * CC + c] * sc;
    }
    if (t == 0)
        g_bias[c] = sh[0] + sh[1] + sh[2] + sh[3] + sh[4] + sh[5] + sh[6];

    if (t < 169) {
        int ty = t / 13, tx = t % 13;
        int dy = ty - PAD, dx = tx - PAD;
        float acc = s[0] * lk_w[c * 169 + t];

        const float* ws[6]   = { w0, w1, w2, w3, w4, w5 };
        const int    KSa[6]  = { 5, 7, 7, 3, 3, 3 };
        const int    DILa[6] = { 1, 1, 2, 3, 4, 5 };
#pragma unroll
        for (int j = 0; j < 6; j++) {
            int r = DILa[j], k = KSa[j];
            if (dy % r == 0 && dx % r == 0) {
                int a  = dy / r + (k - 1) / 2;
                int b2 = dx / r + (k - 1) / 2;
                if (a >= 0 && a < k && b2 >= 0 && b2 < k)
                    acc += s[j + 1] * ws[j][c * k * k + a * k + b2];
            }
        }
        sweq[t] = acc;
    }
    __syncthreads();

    // Packed Toeplitz B: B[k][n] = Weq[k/20][k%20 - n] (valid taps only).
    for (int e = t; e < NKS * 32; e += blockDim.x) {
        int ks  = e >> 5;
        int r   = e & 31;
        int tig = r >> 3, g = r & 7;
        uint32_t bx = 0, by = 0;
#pragma unroll
        for (int half = 0; half < 2; half++) {
            int k = 8 * ks + tig + 4 * half;
            float v = 0.f;
            if (k < 260) {
                int ky  = k / 20;
                int c20 = k - ky * 20;
                int kx  = c20 - g;
                if (kx >= 0 && kx <= 12)
                    v = sweq[ky * 13 + kx];
            }
            if (half == 0) bx = f2tf32(v); else by = f2tf32(v);
        }
        g_B2[c * (NKS * 32) + e] = make_uint2(bx, by);
    }
}

__global__ void __launch_bounds__(NTHR, 3) conv_tc(const float* __restrict__ x,
                                                   float* __restrict__ out)
{
    __shared__ uint32_t sA[2 * TILE];    // two padded 69x68 tiles, tf32 bits
    __shared__ uint2    sB[NKS * 32];    // 8448 B
    __shared__ float    sbias;

    int bid = blockIdx.x;
    int c   = bid & (CC - 1);
    int ib0 = (bid >> 8) * 2;
    int tid = threadIdx.x;

    const float* xim0 = x + (size_t)(ib0 * CC + c) * (HW * HW);
    const float* xim1 = xim0 + (size_t)CC * (HW * HW);

    for (int idx = tid; idx < 2 * TILE; idx += NTHR) {
        int e = idx, img = 0;
        if (e >= TILE) { img = 1; e -= TILE; }
        int r   = e / TCOLS;
        int cc2 = e - r * TCOLS;
        int iy = r - PAD, ix = cc2 - PAD;
        float v = 0.f;
        if ((unsigned)iy < (unsigned)HW && (unsigned)ix < (unsigned)HW)
            v = (img ? xim1 : xim0)[iy * HW + ix];
        sA[idx] = f2tf32(v);
    }
    for (int t = tid; t < NKS * 32; t += NTHR)
        sB[t] = g_B2[c * (NKS * 32) + t];
    if (tid == 0) sbias = g_bias[c];
    __syncthreads();

    int warp = tid >> 5;                 // xb = warp (0..6)
    int lane = tid & 31;
    int g    = lane >> 2;                // groupID 0..7
    int tig  = lane & 3;                 // thread-in-group
    int xb   = warp;
    float bb = sbias;

    // Hoist all B fragments into registers: statically indexed, read-only.
    uint2 breg[NKS];
    {
        const uint2* sBw = sB + tig * 8 + g;
#pragma unroll
        for (int ks = 0; ks < NKS; ks++) breg[ks] = sBw[ks * 32];
    }

#pragma unroll 1
    for (int mt = 0; mt < 7; mt++) {
        int m    = mt * 16 + g;
        int img  = (m >= HW) ? 1 : 0;
        int y    = m - HW * img;
        int m2   = m + 8;
        int img2 = (m2 >= HW) ? 1 : 0;
        int y2   = m2 - HW * img2;

        int base = img * TILE + y * TCOLS + xb * 8 + tig;
        int d8   = (img2 * TILE + y2 * TCOLS) - (img * TILE + y * TCOLS);

        // Two independent accumulator chains (even ks / odd ks).
        float da0 = 0.f, da1 = 0.f, da2 = 0.f, da3 = 0.f;
        float db0 = 0.f, db1 = 0.f, db2 = 0.f, db3 = 0.f;

#pragma unroll
        for (int ks = 0; ks < NKS; ks++) {
            // Compile-time A offsets: 8ks%20 in {0,4,8,12,16}; +tig<=3 never
            // wraps; the +4 operand wraps to the next row when c0==16.
            const int kb   = 8 * ks;
            const int ky0  = kb / 20;
            const int c0   = kb - 20 * ky0;
            const int off0 = ky0 * TCOLS + c0;
            const int off1 = (c0 == 16) ? (ky0 + 1) * TCOLS : off0 + 4;

            uint32_t a0 = sA[base + off0];
            uint32_t a1 = sA[base + d8 + off0];
            uint32_t a2 = sA[base + off1];
            uint32_t a3 = sA[base + d8 + off1];

            if ((ks & 1) == 0) {
                asm volatile(
                    "mma.sync.aligned.m16n8k8.row.col.f32.tf32.tf32.f32 "
                    "{%0,%1,%2,%3}, {%4,%5,%6,%7}, {%8,%9}, {%0,%1,%2,%3};"
                    : "+f"(da0), "+f"(da1), "+f"(da2), "+f"(da3)
                    : "r"(a0), "r"(a1), "r"(a2), "r"(a3),
                      "r"(breg[ks].x), "r"(breg[ks].y));
            } else {
                asm volatile(
                    "mma.sync.aligned.m16n8k8.row.col.f32.tf32.tf32.f32 "
                    "{%0,%1,%2,%3}, {%4,%5,%6,%7}, {%8,%9}, {%0,%1,%2,%3};"
                    : "+f"(db0), "+f"(db1), "+f"(db2), "+f"(db3)
                    : "r"(a0), "r"(a1), "r"(a2), "r"(a3),
                      "r"(breg[ks].x), "r"(breg[ks].y));
            }
        }

        float e0 = da0 + db0, e1 = da1 + db1;
        float e2 = da2 + db2, e3 = da3 + db3;

        float* o0 = out + (size_t)((ib0 + img)  * CC + c) * (HW * HW)
                        + y  * HW + xb * 8 + 2 * tig;
        float* o1 = out + (size_t)((ib0 + img2) * CC + c) * (HW * HW)
                        + y2 * HW + xb * 8 + 2 * tig;
        reinterpret_cast<float2*>(o0)[0] = make_float2(e0 + bb, e1 + bb);
        reinterpret_cast<float2*>(o1)[0] = make_float2(e2 + bb, e3 + bb);
    }
}

extern "C" void kernel_launch(void* const* d_in, const int* in_sizes, int n_in,
                              void* d_out, int out_size)
{
    const float* x    = (const float*)d_in[0];
    const float* lk_w = (const float*)d_in[1];
    const float* w0   = (const float*)d_in[2];
    const float* w1   = (const float*)d_in[3];
    const float* w2   = (const float*)d_in[4];
    const float* w3   = (const float*)d_in[5];
    const float* w4   = (const float*)d_in[6];
    const float* w5   = (const float*)d_in[7];
    const float* g    = (const float*)d_in[8];
    const float* b    = (const float*)d_in[9];
    const float* m    = (const float*)d_in[10];
    const float* v    = (const float*)d_in[11];
    float* out = (float*)d_out;

    prep_kernel<<<CC, 256>>>(lk_w, w0, w1, w2, w3, w4, w5, g, b, m, v);

    int nimg = out_size / (HW * HW * CC);   // 32
    int grid = (nimg / 2) * CC;             // 4096 CTAs
    conv_tc<<<grid, NTHR>>>(x, out);
}

// round 17
// speedup vs baseline: 1.8750x; 1.8750x over previous
#include <cuda_runtime.h>
#include <cuda_fp16.h>
#include <cstdint>

// DilatedReparamBlock == single 13x13 depthwise conv + per-channel bias.
//
// R16: fp16 m16n8k16 Toeplitz implicit GEMM. fp16 mantissa (10 bits) ==
// tf32 mantissa, fp32 accumulate -> same accuracy class as the measured
// 2.7e-4, but half the A bytes, half the MMA count, and consecutive-k
// fragment pairs = single LDS32 per operand. Per-k16-block k-slot
// permutation (baked into B by prep) keeps every A load a reg+imm LDS32
// even for row-straddling blocks. B lives in 17 uint2 regs (from L2).

#define CC    256
#define HW    56
#define PAD   6
#define SH    72                 // f16 elems per tile row (g-step 4 mod 32 banks)
#define TROWS 69                 // 68 padded rows + 1 zero row
#define TILEH (TROWS * SH)       // 4968 f16
#define NB    17                 // k16 blocks: 13*20=260 -> 272 padded
#define NTHR  224                // 7 warps; warp w <-> xb = w

__device__ uint2 g_Bh[CC * NB * 32];  // per (c, block, lane): packed f16x2 (b0,b1)
__device__ float g_bias[CC];

__global__ void prep_kernel(const float* __restrict__ lk_w,
                            const float* __restrict__ w0, const float* __restrict__ w1,
                            const float* __restrict__ w2, const float* __restrict__ w3,
                            const float* __restrict__ w4, const float* __restrict__ w5,
                            const float* __restrict__ gamma, const float* __restrict__ beta,
                            const float* __restrict__ mean,  const float* __restrict__ var)
{
    __shared__ float sweq[169];
    int c = blockIdx.x;
    int t = threadIdx.x;

    float s[7], sh[7];
#pragma unroll
    for (int i = 0; i < 7; i++) {
        float sc = gamma[i * CC + c] * rsqrtf(var[i * CC + c] + 1e-5f);
        s[i]  = sc;
        sh[i] = beta[i * CC + c] - mean[i * CC + c] * sc;
    }
    if (t == 0)
        g_bias[c] = sh[0] + sh[1] + sh[2] + sh[3] + sh[4] + sh[5] + sh[6];

    if (t < 169) {
        int ty = t / 13, tx = t % 13;
        int dy = ty - PAD, dx = tx - PAD;
        float acc = s[0] * lk_w[c * 169 + t];

        const float* ws[6]   = { w0, w1, w2, w3, w4, w5 };
        const int    KSa[6]  = { 5, 7, 7, 3, 3, 3 };
        const int    DILa[6] = { 1, 1, 2, 3, 4, 5 };
#pragma unroll
        for (int j = 0; j < 6; j++) {
            int r = DILa[j], k = KSa[j];
            if (dy % r == 0 && dx % r == 0) {
                int a  = dy / r + (k - 1) / 2;
                int b2 = dx / r + (k - 1) / 2;
                if (a >= 0 && a < k && b2 >= 0 && b2 < k)
                    acc += s[j + 1] * ws[j][c * k * k + a * k + b2];
            }
        }
        sweq[t] = acc;
    }
    __syncthreads();

    // B with per-block k-slot permutation. Lane (g = lane>>2, tig = lane&3)
    // holds pairs j = tig (b0) and j = tig+4 (b1); pair j covers window
    // positions (p0, p0+1) of one row.
    for (int e = t; e < NB * 32; e += blockDim.x) {
        int b    = e >> 5;
        int lane = e & 31;
        int g    = lane >> 2, tig = lane & 3;

        int kb = 16 * b;
        int ky = kb / 20;
        int c0 = kb - 20 * ky;
        int LA2 = (c0 <= 4) ? 8 : (20 - c0) / 2;   // pairs in row ky

        uint32_t pk[2];
#pragma unroll
        for (int h = 0; h < 2; h++) {
            int j = tig + 4 * h;
            int row, p0;
            if (j < LA2) { row = ky;     p0 = c0 + 2 * j; }
            else         { row = ky + 1; p0 = 2 * (j - LA2); }
            float lo = 0.f, hi = 0.f;
            if (row <= 12) {
                int kx0 = p0 - g;
                int kx1 = p0 + 1 - g;
                if (kx0 >= 0 && kx0 <= 12) lo = sweq[row * 13 + kx0];
                if (kx1 >= 0 && kx1 <= 12) hi = sweq[row * 13 + kx1];
            }
            __half2 hp = __floats2half2_rn(lo, hi);   // low = slot 2j
            pk[h] = *reinterpret_cast<uint32_t*>(&hp);
        }
        g_Bh[c * (NB * 32) + e] = make_uint2(pk[0], pk[1]);
    }
}

__global__ void __launch_bounds__(NTHR, 4) conv_tc(const float* __restrict__ x,
                                                   float* __restrict__ out)
{
    __shared__ __half sxh[2 * TILEH];    // two f16 tiles, 19872 B

    int bid = blockIdx.x;
    int c   = bid & (CC - 1);
    int ib0 = (bid >> 8) * 2;
    int tid = threadIdx.x;

    const float* xim0 = x + (size_t)(ib0 * CC + c) * (HW * HW);
    const float* xim1 = xim0 + (size_t)CC * (HW * HW);

    // Fill padded f16 tiles (zero halo; cols 68..71 and row 68 zero).
    for (int idx = tid; idx < 2 * TILEH; idx += NTHR) {
        int e = idx, img = 0;
        if (e >= TILEH) { img = 1; e -= TILEH; }
        int r   = e / SH;
        int col = e - r * SH;
        int iy = r - PAD, ix = col - PAD;
        float v = 0.f;
        if ((unsigned)iy < (unsigned)HW && (unsigned)ix < (unsigned)HW)
            v = (img ? xim1 : xim0)[iy * HW + ix];
        sxh[idx] = __float2half_rn(v);
    }

    int warp = tid >> 5;
    int lane = tid & 31;
    int g    = lane >> 2;
    int tig  = lane & 3;
    int xb   = warp;
    float bb = g_bias[c];

    // B fragments: 17 x uint2 straight from L2 (reused by 16 CTAs).
    uint2 breg[NB];
    {
        const uint2* gb = g_Bh + c * (NB * 32) + lane;
#pragma unroll
        for (int b = 0; b < NB; b++) breg[b] = gb[b * 32];
    }
    __syncthreads();

    const uint32_t t2 = 2 * tig;
    const uint32_t r1add = (tig >= 2) ? (SH - 20) : 0;   // row-straddle fixup

#pragma unroll 1
    for (int mt = 0; mt < 7; mt++) {
        int m    = mt * 16 + g;
        int img  = (m >= HW) ? 1 : 0;
        int y    = m - HW * img;
        int m2   = m + 8;
        int img2 = (m2 >= HW) ? 1 : 0;
        int y2   = m2 - HW * img2;

        int base = img * TILEH + y * SH + xb * 8;
        int d8   = (img2 * TILEH + y2 * SH) - (img * TILEH + y * SH);

        const __half* R0  = sxh + base + t2;
        const __half* R0d = R0 + d8;
        const __half* R1  = R0 + r1add;
        const __half* R1d = R1 + d8;

        float d0 = 0.f, d1 = 0.f, d2 = 0.f, d3 = 0.f;

#pragma unroll
        for (int b = 0; b < NB; b++) {
            const int kb = 16 * b;
            const int ky = kb / 20;
            const int c0 = kb - 20 * ky;
            const int o  = ky * SH;

            uint32_t a0, a1, a2, a3;
            if (c0 == 0 || c0 == 4) {
                a0 = *(const uint32_t*)(R0  + o + c0);
                a1 = *(const uint32_t*)(R0d + o + c0);
                a2 = *(const uint32_t*)(R0  + o + c0 + 8);
                a3 = *(const uint32_t*)(R0d + o + c0 + 8);
            } else if (c0 == 8) {
                a0 = *(const uint32_t*)(R0  + o + 8);
                a1 = *(const uint32_t*)(R0d + o + 8);
                a2 = *(const uint32_t*)(R1  + o + 16);
                a3 = *(const uint32_t*)(R1d + o + 16);
            } else if (c0 == 12) {
                a0 = *(const uint32_t*)(R0  + o + 12);
                a1 = *(const uint32_t*)(R0d + o + 12);
                a2 = *(const uint32_t*)(R0  + o + SH);
                a3 = *(const uint32_t*)(R0d + o + SH);
            } else {               // c0 == 16
                a0 = *(const uint32_t*)(R1  + o + 16);
                a1 = *(const uint32_t*)(R1d + o + 16);
                a2 = *(const uint32_t*)(R0  + o + SH + 4);
                a3 = *(const uint32_t*)(R0d + o + SH + 4);
            }

            asm volatile(
                "mma.sync.aligned.m16n8k16.row.col.f32.f16.f16.f32 "
                "{%0,%1,%2,%3}, {%4,%5,%6,%7}, {%8,%9}, {%0,%1,%2,%3};"
                : "+f"(d0), "+f"(d1), "+f"(d2), "+f"(d3)
                : "r"(a0), "r"(a1), "r"(a2), "r"(a3),
                  "r"(breg[b].x), "r"(breg[b].y));
        }

        float* o0 = out + (size_t)((ib0 + img)  * CC + c) * (HW * HW)
                        + y  * HW + xb * 8 + 2 * tig;
        float* o1 = out + (size_t)((ib0 + img2) * CC + c) * (HW * HW)
                        + y2 * HW + xb * 8 + 2 * tig;
        reinterpret_cast<float2*>(o0)[0] = make_float2(d0 + bb, d1 + bb);
        reinterpret_cast<float2*>(o1)[0] = make_float2(d2 + bb, d3 + bb);
    }
}

extern "C" void kernel_launch(void* const* d_in, const int* in_sizes, int n_in,
                              void* d_out, int out_size)
{
    const float* x    = (const float*)d_in[0];
    const float* lk_w = (const float*)d_in[1];
    const float* w0   = (const float*)d_in[2];
    const float* w1   = (const float*)d_in[3];
    const float* w2   = (const float*)d_in[4];
    const float* w3   = (const float*)d_in[5];
    const float* w4   = (const float*)d_in[6];
    const float* w5   = (const float*)d_in[7];
    const float* g    = (const float*)d_in[8];
    const float* b    = (const float*)d_in[9];
    const float* m    = (const float*)d_in[10];
    const float* v    = (const float*)d_in[11];
    float* out = (float*)d_out;

    prep_kernel<<<CC, 192>>>(lk_w, w0, w1, w2, w3, w4, w5, g, b, m, v);

    int nimg = out_size / (HW * HW * CC);   // 32
    int grid = (nimg / 2) * CC;             // 4096 CTAs
    conv_tc<<<grid, NTHR>>>(x, out);
}